// round 3
// baseline (speedup 1.0000x reference)
#include <cuda_runtime.h>

// QWT collapses: filt(x,h) = x * sum(h) (scalar), downsample is linear.
// Every output sub-band = coef * D, D = bicubic stride-2 downsample of image.
// Inputs: image (16,3,512,512) f32, gl/gh/fl/fh (30 f32 each)
// Output: concat of 4 tensors, each (16,12,256,256) f32.

#define W0 (-0.09375f)
#define W1 ( 0.59375f)
#define W2 ( 0.59375f)
#define W3 (-0.09375f)

__device__ float g_coef[16];

__global__ void coef_kernel(const float* __restrict__ gl, const float* __restrict__ gh,
                            const float* __restrict__ fl, const float* __restrict__ fh) {
    if (threadIdx.x == 0) {
        float A = 0.f, B = 0.f, C = 0.f, D = 0.f;
        for (int k = 0; k < 30; k++) { A += gl[k]; B += gh[k]; C += fl[k]; D += fh[k]; }
        for (int t = 0; t < 4; t++) {
            for (int q = 0; q < 4; q++) {
                float f1 = (t < 2) ? ((q & 1) ? C : A) : ((q & 1) ? D : B);
                float f2 = ((t & 1) == 0) ? ((q & 2) ? C : A) : ((q & 2) ? D : B);
                g_coef[t * 4 + q] = f1 * f2;
            }
        }
    }
}

// 256 threads per block. Block handles 4 output rows x 256 cols of one image.
// Grid: (64 row-groups, 48 images).
__global__ __launch_bounds__(256) void qwt_down_kernel(const float* __restrict__ img,
                                                       float* __restrict__ out) {
    __shared__ float srows[10][512];   // 10 source rows (coalesced-staged)
    __shared__ float vrow[4][512];     // vertically-filtered rows
    __shared__ float sc[16];

    const int tid  = threadIdx.x;
    const int i0   = blockIdx.x * 4;   // first output row of this block
    const int imgi = blockIdx.y;       // b*3 + c

    if (tid < 16) sc[tid] = g_coef[tid];

    const float* src = img + (size_t)imgi * 512 * 512;

    // ---- Stage A: coalesced float4 load of 10 source rows (edge-clamped) ----
    const int r_base = 2 * i0 - 1;
#pragma unroll
    for (int l = 0; l < 5; l++) {
        int idx = tid + l * 256;            // 0..1279 (10 rows * 128 float4)
        int k   = idx >> 7;                 // source-row slot 0..9
        int c4  = (idx & 127) << 2;         // col base
        int r   = min(511, max(0, r_base + k));
        *(float4*)&srows[k][c4] = *(const float4*)&src[r * 512 + c4];
    }
    __syncthreads();

    // ---- Stage B1: vertical 4-tap pass, float4, conflict-free ----
#pragma unroll
    for (int l = 0; l < 2; l++) {
        int idx = tid + l * 256;            // 0..511
        int y   = idx >> 7;                 // output row within block 0..3
        int c4  = (idx & 127) << 2;
        float4 a = *(float4*)&srows[2 * y + 0][c4];
        float4 b = *(float4*)&srows[2 * y + 1][c4];
        float4 c = *(float4*)&srows[2 * y + 2][c4];
        float4 d = *(float4*)&srows[2 * y + 3][c4];
        float4 v;
        v.x = W0 * a.x + W1 * b.x + W2 * c.x + W3 * d.x;
        v.y = W0 * a.y + W1 * b.y + W2 * c.y + W3 * d.y;
        v.z = W0 * a.z + W1 * b.z + W2 * c.z + W3 * d.z;
        v.w = W0 * a.w + W1 * b.w + W2 * c.w + W3 * d.w;
        *(float4*)&vrow[y][c4] = v;
    }
    __syncthreads();

    // ---- Stage B2: horizontal pass + 16 scaled fan-out stores ----
    const int x = tid & 63;                 // output col base (stride-64 scheme)
    const int y = tid >> 6;                 // output row within block
    const int i = i0 + y;

    float d[4];
#pragma unroll
    for (int m = 0; m < 4; m++) {
        int j  = x + 64 * m;
        int c0 = max(0, 2 * j - 1);
        int c3 = min(511, 2 * j + 2);
        d[m] = W0 * vrow[y][c0] + W1 * vrow[y][2 * j]
             + W2 * vrow[y][2 * j + 1] + W3 * vrow[y][c3];
    }

    const int b = imgi / 3;
    const int c = imgi % 3;
    // out[t][b, q*3+c, i, j]  with tensor size 16*12*256*256
    float* p = out + ((size_t)(b * 12 + c) * 256 + i) * 256 + x;

#pragma unroll
    for (int t = 0; t < 4; t++) {
        float* pt = p + (size_t)t * (16 * 12 * 256 * 256);
#pragma unroll
        for (int q = 0; q < 4; q++) {
            float s = sc[t * 4 + q];
#pragma unroll
            for (int m = 0; m < 4; m++)
                pt[q * (3 * 256 * 256) + m * 64] = s * d[m];
        }
    }
}

extern "C" void kernel_launch(void* const* d_in, const int* in_sizes, int n_in,
                              void* d_out, int out_size) {
    const float* image = (const float*)d_in[0];
    const float* gl    = (const float*)d_in[1];
    const float* gh    = (const float*)d_in[2];
    const float* fl    = (const float*)d_in[3];
    const float* fh    = (const float*)d_in[4];
    float* out = (float*)d_out;

    coef_kernel<<<1, 32>>>(gl, gh, fl, fh);

    dim3 block(256, 1, 1);
    dim3 grid(64, 48, 1);
    qwt_down_kernel<<<grid, block>>>(image, out);
}

// round 5
// speedup vs baseline: 1.0209x; 1.0209x over previous
#include <cuda_runtime.h>

// QWT collapses: filt(x,h) = x * sum(h) (scalar), downsample is linear.
// Every output sub-band = coef * D, D = bicubic stride-2 downsample of image.
// Inputs: image (16,3,512,512) f32, gl/gh/fl/fh (30 f32 each)
// Output: concat of 4 tensors, each (16,12,256,256) f32.
//
// NOTE: filter sums MUST be computed sequentially (k=0..29) — Σgh/Σfl/Σfh are
// cancellation sums ~0 whose fp32 value depends on summation order; a tree
// reduction changes the rounding and blows up rel_err on the near-zero bands.

#define W0 (-0.09375f)
#define W1 ( 0.59375f)
#define W2 ( 0.59375f)
#define W3 (-0.09375f)

// 256 threads/block. Block: 4 output rows x 256 cols of one image.
// Grid: (64 row-groups, 48 images).
__global__ __launch_bounds__(256) void qwt_down_kernel(const float* __restrict__ img,
                                                       const float* __restrict__ gl,
                                                       const float* __restrict__ gh,
                                                       const float* __restrict__ fl,
                                                       const float* __restrict__ fh,
                                                       float* __restrict__ out) {
    __shared__ float srows[10][512];   // 10 staged source rows
    __shared__ float sc[16];           // 16 sub-band coefficients

    const int tid  = threadIdx.x;
    const int i0   = blockIdx.x * 4;   // first output row of this block
    const int imgi = blockIdx.y;       // b*3 + c

    // ---- warp 0: sequential filter sums (order-sensitive!) + 16 coefs ----
    // All 32 lanes compute redundantly (uniform; broadcast loads); lanes<16 write.
    if (tid < 32) {
        float A = 0.f, B = 0.f, C = 0.f, D = 0.f;
#pragma unroll
        for (int k = 0; k < 30; k++) {
            A += gl[k]; B += gh[k]; C += fl[k]; D += fh[k];
        }
        if (tid < 16) {
            int t = tid >> 2, q = tid & 3;
            float f1 = (t < 2)        ? ((q & 1) ? C : A) : ((q & 1) ? D : B);
            float f2 = ((t & 1) == 0) ? ((q & 2) ? C : A) : ((q & 2) ? D : B);
            sc[tid] = f1 * f2;
        }
    }

    const float* src = img + (size_t)imgi * 512 * 512;

    // ---- Stage A: coalesced float4 staging of 10 source rows (edge-clamped) ----
    const int r_base = 2 * i0 - 1;
#pragma unroll
    for (int l = 0; l < 5; l++) {
        int idx = tid + l * 256;            // 0..1279 (10 rows * 128 float4)
        int k   = idx >> 7;                 // row slot 0..9
        int c4  = (idx & 127) << 2;         // col base
        int r   = min(511, max(0, r_base + k));
        *(float4*)&srows[k][c4] = *(const float4*)&src[r * 512 + c4];
    }
    __syncthreads();

    // ---- Stage B: fused vertical+horizontal pass, 4 consecutive outputs/thread ----
    const int tx = tid & 63;                // col group: outputs j0..j0+3
    const int y  = tid >> 6;                // output row within block
    const int j0 = 4 * tx;
    const int i  = i0 + y;

    const int cl = max(0, 8 * tx - 1);      // left clamped source col
    const int cr = min(511, 8 * tx + 8);    // right clamped source col

    float v[10];
#pragma unroll
    for (int q = 0; q < 10; q++) v[q] = 0.f;

#pragma unroll
    for (int r = 0; r < 4; r++) {
        const float w = (r == 0) ? W0 : (r == 1) ? W1 : (r == 2) ? W2 : W3;
        const float* row = srows[2 * y + r];
        float4 a0 = *(const float4*)&row[8 * tx];
        float4 a1 = *(const float4*)&row[8 * tx + 4];
        v[0] += w * row[cl];
        v[1] += w * a0.x;  v[2] += w * a0.y;  v[3] += w * a0.z;  v[4] += w * a0.w;
        v[5] += w * a1.x;  v[6] += w * a1.y;  v[7] += w * a1.z;  v[8] += w * a1.w;
        v[9] += w * row[cr];
    }

    float d0 = W0 * v[0] + W1 * v[1] + W2 * v[2] + W3 * v[3];
    float d1 = W0 * v[2] + W1 * v[3] + W2 * v[4] + W3 * v[5];
    float d2 = W0 * v[4] + W1 * v[5] + W2 * v[6] + W3 * v[7];
    float d3 = W0 * v[6] + W1 * v[7] + W2 * v[8] + W3 * v[9];

    const int b = imgi / 3;
    const int c = imgi % 3;
    // out[t][b, q*3+c, i, j], each tensor 16*12*256*256
    float* p = out + ((size_t)(b * 12 + c) * 256 + i) * 256 + j0;

#pragma unroll
    for (int t = 0; t < 4; t++) {
        float* pt = p + (size_t)t * (16 * 12 * 256 * 256);
#pragma unroll
        for (int q = 0; q < 4; q++) {
            float s = sc[t * 4 + q];
            float4 o = make_float4(s * d0, s * d1, s * d2, s * d3);
            *(float4*)&pt[q * (3 * 256 * 256)] = o;
        }
    }
}

extern "C" void kernel_launch(void* const* d_in, const int* in_sizes, int n_in,
                              void* d_out, int out_size) {
    const float* image = (const float*)d_in[0];
    const float* gl    = (const float*)d_in[1];
    const float* gh    = (const float*)d_in[2];
    const float* fl    = (const float*)d_in[3];
    const float* fh    = (const float*)d_in[4];
    float* out = (float*)d_out;

    dim3 block(256, 1, 1);
    dim3 grid(64, 48, 1);
    qwt_down_kernel<<<grid, block>>>(image, gl, gh, fl, fh, out);
}

// round 6
// speedup vs baseline: 1.0734x; 1.0514x over previous
#include <cuda_runtime.h>

// QWT collapses: filt(x,h) = x * sum(h) (scalar), downsample is linear.
// Every output sub-band = coef * D, D = bicubic stride-2 downsample of image.
// Inputs: image (16,3,512,512) f32, gl/gh/fl/fh (30 f32 each)
// Output: concat of 4 tensors, each (16,12,256,256) f32.
//
// NOTE: filter sums MUST be computed sequentially (k=0..29) — Σgh/Σfl/Σfh are
// cancellation sums ~0 whose fp32 value depends on summation order.

#define W0 (-0.09375f)
#define W1 ( 0.59375f)
#define W2 ( 0.59375f)
#define W3 (-0.09375f)

// 256 threads/block. Block: 4 output rows x 256 cols of one image.
// Grid: (64 row-groups, 48 images). Single launch.
__global__ __launch_bounds__(256, 6) void qwt_down_kernel(const float* __restrict__ img,
                                                          const float* __restrict__ gl,
                                                          const float* __restrict__ gh,
                                                          const float* __restrict__ fl,
                                                          const float* __restrict__ fh,
                                                          float* __restrict__ out) {
    __shared__ float srows[10][512];   // 10 staged source rows
    __shared__ float vrow[4][512];     // vertically-filtered rows
    __shared__ float sc[16];           // 16 sub-band coefficients

    const int tid  = threadIdx.x;
    const int i0   = blockIdx.x * 4;   // first output row of this block
    const int imgi = blockIdx.y;       // b*3 + c

    // ---- warp 0: sequential filter sums (order-sensitive!) + 16 coefs ----
    if (tid < 32) {
        float A = 0.f, B = 0.f, C = 0.f, D = 0.f;
#pragma unroll
        for (int k = 0; k < 30; k++) {
            A += gl[k]; B += gh[k]; C += fl[k]; D += fh[k];
        }
        if (tid < 16) {
            int t = tid >> 2, q = tid & 3;
            float f1 = (t < 2)        ? ((q & 1) ? C : A) : ((q & 1) ? D : B);
            float f2 = ((t & 1) == 0) ? ((q & 2) ? C : A) : ((q & 2) ? D : B);
            sc[tid] = f1 * f2;
        }
    }

    const float* src = img + (size_t)imgi * 512 * 512;

    // ---- Stage A: coalesced float4 staging of 10 source rows (edge-clamped) ----
    const int r_base = 2 * i0 - 1;
#pragma unroll
    for (int l = 0; l < 5; l++) {
        int idx = tid + l * 256;            // 0..1279 (10 rows * 128 float4)
        int k   = idx >> 7;                 // row slot 0..9
        int c4  = (idx & 127) << 2;         // col base
        int r   = min(511, max(0, r_base + k));
        *(float4*)&srows[k][c4] = *(const float4*)&src[r * 512 + c4];
    }
    __syncthreads();

    // ---- Stage B1: vertical 4-tap pass, float4, conflict-free ----
#pragma unroll
    for (int l = 0; l < 2; l++) {
        int idx = tid + l * 256;            // 0..511
        int y   = idx >> 7;                 // output row within block 0..3
        int c4  = (idx & 127) << 2;
        float4 a = *(float4*)&srows[2 * y + 0][c4];
        float4 b = *(float4*)&srows[2 * y + 1][c4];
        float4 c = *(float4*)&srows[2 * y + 2][c4];
        float4 d = *(float4*)&srows[2 * y + 3][c4];
        float4 v;
        v.x = W0 * a.x + W1 * b.x + W2 * c.x + W3 * d.x;
        v.y = W0 * a.y + W1 * b.y + W2 * c.y + W3 * d.y;
        v.z = W0 * a.z + W1 * b.z + W2 * c.z + W3 * d.z;
        v.w = W0 * a.w + W1 * b.w + W2 * c.w + W3 * d.w;
        *(float4*)&vrow[y][c4] = v;
    }
    __syncthreads();

    // ---- Stage B2: horizontal pass + 16 scaled fan-out stores (stride-64) ----
    const int x = tid & 63;                 // output col base
    const int y = tid >> 6;                 // output row within block
    const int i = i0 + y;

    float d[4];
#pragma unroll
    for (int m = 0; m < 4; m++) {
        int j  = x + 64 * m;
        int c0 = max(0, 2 * j - 1);
        int c3 = min(511, 2 * j + 2);
        d[m] = W0 * vrow[y][c0] + W1 * vrow[y][2 * j]
             + W2 * vrow[y][2 * j + 1] + W3 * vrow[y][c3];
    }

    const int b = imgi / 3;
    const int c = imgi % 3;
    // out[t][b, q*3+c, i, j]  with tensor size 16*12*256*256
    float* p = out + ((size_t)(b * 12 + c) * 256 + i) * 256 + x;

#pragma unroll
    for (int t = 0; t < 4; t++) {
        float* pt = p + (size_t)t * (16 * 12 * 256 * 256);
#pragma unroll
        for (int q = 0; q < 4; q++) {
            float s = sc[t * 4 + q];
#pragma unroll
            for (int m = 0; m < 4; m++)
                __stcs(&pt[q * (3 * 256 * 256) + m * 64], s * d[m]);
        }
    }
}

extern "C" void kernel_launch(void* const* d_in, const int* in_sizes, int n_in,
                              void* d_out, int out_size) {
    const float* image = (const float*)d_in[0];
    const float* gl    = (const float*)d_in[1];
    const float* gh    = (const float*)d_in[2];
    const float* fl    = (const float*)d_in[3];
    const float* fh    = (const float*)d_in[4];
    float* out = (float*)d_out;

    dim3 block(256, 1, 1);
    dim3 grid(64, 48, 1);
    qwt_down_kernel<<<grid, block>>>(image, gl, gh, fl, fh, out);
}